// round 2
// baseline (speedup 1.0000x reference)
#include <cuda_runtime.h>
#include <cstdint>
#include <cstddef>

#define T_SEQ 1024
#define HID   256
#define ROWS  64

// Scratch (sanctioned: __device__ globals, no runtime allocation)
__device__ float    g_h[2 * ROWS * HID];                       // double-buffered hidden state
__device__ float    g_seqA[(size_t)ROWS * T_SEQ * HID];        // layer0 output sequence (64 MB)
__device__ float    g_seqB[(size_t)ROWS * T_SEQ * HID];        // layer1 output sequence (64 MB)
__device__ float    g_mask[ROWS * T_SEQ];                      // Masking(mask_value=0)
__device__ unsigned g_bar[12];                                 // barrier counters [layer][batch-group]

// ---------------------------------------------------------------------------
// Init: zero barrier counters, compute mask[row][t] = any(x[row][t][:] != 0)
// x viewed as [64 rows][1024 t][128 f]. One warp per (row,t) position.
// ---------------------------------------------------------------------------
__global__ void init_kernel(const float* __restrict__ x)
{
    if (blockIdx.x == 0 && threadIdx.x < 12) g_bar[threadIdx.x] = 0u;

    int warp = (int)((blockIdx.x * blockDim.x + threadIdx.x) >> 5);
    int lane = threadIdx.x & 31;
    if (warp < ROWS * T_SEQ) {
        const float4* p = reinterpret_cast<const float4*>(x) + (size_t)warp * 32; // 128 floats
        float4 v = p[lane];
        bool nz = (v.x != 0.0f) || (v.y != 0.0f) || (v.z != 0.0f) || (v.w != 0.0f);
        unsigned bl = __ballot_sync(0xffffffffu, nz);
        if (lane == 0) g_mask[warp] = bl ? 1.0f : 0.0f;
    }
}

// ---------------------------------------------------------------------------
// Persistent masked-LSTM layer kernel.
// Grid = 128 blocks: bg = blockIdx.x & 3 (16 batch rows each),
//                    cg = blockIdx.x >> 2 (8 hidden units each -> 32 gate cols).
// Each step: z[16 x 32] = x_t @ W_slice + h @ U_slice + b, gates, state update.
// Microtile: 256 threads = 16 output tiles (4 batch x 8 cols) x 16 split-K.
// Sync: per-batch-group monotonic-counter spin barrier (32 blocks, all resident).
// ---------------------------------------------------------------------------
__global__ void __launch_bounds__(256, 1)
lstm_layer_kernel(const float* __restrict__ x0, int Kin,
                  const float* __restrict__ W, const float* __restrict__ U,
                  const float* __restrict__ bias, int layer)
{
    extern __shared__ float sm[];
    float* w_sh = sm;                    // [32][Kin]  transposed W slice
    float* u_sh = w_sh + 32 * Kin;       // [32][256]  transposed U slice
    float* x_sh = u_sh + 32 * HID;       // [16][Kin]
    float* h_sh = x_sh + 16 * Kin;       // [16][256]
    float* p_sh = h_sh + 16 * HID;       // [512][17]  split-K partials (padded)
    float* z_sh = p_sh + 512 * 17;       // [512]
    float* b_sh = z_sh + 512;            // [32]

    const float* in_seq = (layer == 0) ? x0 : (layer == 1 ? g_seqA : g_seqB);
    float*       seq_out = (layer == 0) ? g_seqA : (layer == 1 ? g_seqB : nullptr);

    const int tid  = threadIdx.x;
    const int bg   = blockIdx.x & 3;
    const int cg   = blockIdx.x >> 2;
    const int row0 = bg * 16;

    // --- one-time weight staging (gathered gate columns, transposed to [col][k]) ---
    for (int idx = tid; idx < 32 * Kin; idx += 256) {
        int c = idx / Kin, k = idx - c * Kin;
        int gcol = ((c >> 3) << 8) + (cg << 3) + (c & 7);   // gate*256 + unit
        w_sh[idx] = W[(size_t)k * 1024 + gcol];
    }
    for (int idx = tid; idx < 32 * HID; idx += 256) {
        int c = idx >> 8, k = idx & 255;
        int gcol = ((c >> 3) << 8) + (cg << 3) + (c & 7);
        u_sh[idx] = U[(size_t)k * 1024 + gcol];
    }
    if (tid < 32) b_sh[tid] = bias[((tid >> 3) << 8) + (cg << 3) + (tid & 7)];

    const int sk   = tid & 15;        // split-K id
    const int tile = tid >> 4;
    const int bq   = tile & 3;        // batch quad (4 rows)
    const int cqg  = tile >> 2;       // gate / col-group (8 cols)

    float c_reg = 0.0f;               // cell state for thread's (b,u), tid<128
    unsigned* barp = &g_bar[layer * 4 + bg];
    const int f4 = Kin >> 2;

    for (int t = 0; t < T_SEQ; t++) {
        // --- stage h(t-1): zeros at t=0, else from parity buffer written last step ---
        if (t == 0) {
            float4 z4 = make_float4(0.f, 0.f, 0.f, 0.f);
            for (int idx = tid; idx < (16 * HID) / 4; idx += 256)
                reinterpret_cast<float4*>(h_sh)[idx] = z4;
        } else {
            const float4* src = reinterpret_cast<const float4*>(
                g_h + (size_t)(t & 1) * ROWS * HID + row0 * HID);
            for (int idx = tid; idx < (16 * HID) / 4; idx += 256)
                reinterpret_cast<float4*>(h_sh)[idx] = src[idx];
        }
        // --- stage x_t for our 16 rows ---
        for (int idx = tid; idx < 16 * f4; idx += 256) {
            int r = idx / f4, kk = idx - r * f4;
            reinterpret_cast<float4*>(x_sh)[idx] =
                reinterpret_cast<const float4*>(in_seq + ((size_t)(row0 + r) * T_SEQ + t) * Kin)[kk];
        }
        __syncthreads();

        // --- z = x_t@W + h@U, microtiled partials ---
        float acc[4][8];
        #pragma unroll
        for (int r = 0; r < 4; r++)
            #pragma unroll
            for (int j = 0; j < 8; j++) acc[r][j] = 0.0f;

        {   // input part
            const float* xb = x_sh + (bq * 4) * Kin;
            const float* wb = w_sh + (cqg * 8) * Kin;
            const int nch = Kin >> 6;   // k4-chunks per thread
            for (int i = 0; i < nch; i++) {
                int k = (sk + (i << 4)) << 2;
                float4 a0 = *reinterpret_cast<const float4*>(xb + k);
                float4 a1 = *reinterpret_cast<const float4*>(xb + Kin + k);
                float4 a2 = *reinterpret_cast<const float4*>(xb + 2 * Kin + k);
                float4 a3 = *reinterpret_cast<const float4*>(xb + 3 * Kin + k);
                #pragma unroll
                for (int j = 0; j < 8; j++) {
                    float4 u = *reinterpret_cast<const float4*>(wb + j * Kin + k);
                    acc[0][j] += a0.x*u.x + a0.y*u.y + a0.z*u.z + a0.w*u.w;
                    acc[1][j] += a1.x*u.x + a1.y*u.y + a1.z*u.z + a1.w*u.w;
                    acc[2][j] += a2.x*u.x + a2.y*u.y + a2.z*u.z + a2.w*u.w;
                    acc[3][j] += a3.x*u.x + a3.y*u.y + a3.z*u.z + a3.w*u.w;
                }
            }
        }
        {   // recurrent part (K = 256 fixed)
            const float* hb = h_sh + (bq * 4) * HID;
            const float* ub = u_sh + (cqg * 8) * HID;
            #pragma unroll
            for (int i = 0; i < 4; i++) {
                int k = (sk + (i << 4)) << 2;
                float4 a0 = *reinterpret_cast<const float4*>(hb + k);
                float4 a1 = *reinterpret_cast<const float4*>(hb + HID + k);
                float4 a2 = *reinterpret_cast<const float4*>(hb + 2 * HID + k);
                float4 a3 = *reinterpret_cast<const float4*>(hb + 3 * HID + k);
                #pragma unroll
                for (int j = 0; j < 8; j++) {
                    float4 u = *reinterpret_cast<const float4*>(ub + j * HID + k);
                    acc[0][j] += a0.x*u.x + a0.y*u.y + a0.z*u.z + a0.w*u.w;
                    acc[1][j] += a1.x*u.x + a1.y*u.y + a1.z*u.z + a1.w*u.w;
                    acc[2][j] += a2.x*u.x + a2.y*u.y + a2.z*u.z + a2.w*u.w;
                    acc[3][j] += a3.x*u.x + a3.y*u.y + a3.z*u.z + a3.w*u.w;
                }
            }
        }
        #pragma unroll
        for (int r = 0; r < 4; r++)
            #pragma unroll
            for (int j = 0; j < 8; j++)
                p_sh[((bq * 4 + r) * 32 + cqg * 8 + j) * 17 + sk] = acc[r][j];
        __syncthreads();

        // --- split-K reduction: 2 outputs per thread ---
        {
            int o = tid;
            float z = b_sh[o & 31];
            #pragma unroll
            for (int s2 = 0; s2 < 16; s2++) z += p_sh[o * 17 + s2];
            z_sh[o] = z;
            o = tid + 256;
            float z2 = b_sh[o & 31];
            #pragma unroll
            for (int s2 = 0; s2 < 16; s2++) z2 += p_sh[o * 17 + s2];
            z_sh[o] = z2;
        }
        __syncthreads();

        // --- gates + masked state update: thread (b_local,u), tid<128 ---
        if (tid < 128) {
            int blc = tid >> 3, u = tid & 7;
            float zi = z_sh[blc * 32 + u];
            float zf = z_sh[blc * 32 + 8 + u];
            float zg = z_sh[blc * 32 + 16 + u];
            float zo = z_sh[blc * 32 + 24 + u];
            float si = 1.0f / (1.0f + expf(-zi));
            float sf = 1.0f / (1.0f + expf(-zf));
            float so = 1.0f / (1.0f + expf(-zo));
            float cn = sf * c_reg + si * tanhf(zg);
            float hn = so * tanhf(cn);
            float m  = g_mask[(row0 + blc) * T_SEQ + t];
            int j = (cg << 3) + u;
            if (m < 0.5f) { cn = c_reg; hn = h_sh[blc * HID + j]; }  // keras carry
            c_reg = cn;
            int row = row0 + blc;
            g_h[(size_t)((t + 1) & 1) * ROWS * HID + row * HID + j] = hn;
            if (seq_out) seq_out[((size_t)row * T_SEQ + t) * HID + j] = hn;
        }
        __syncthreads();

        // --- batch-group barrier (monotonic counter, 32 co-resident blocks) ---
        if (tid == 0) {
            __threadfence();
            atomicAdd(barp, 1u);
            unsigned tgt = 32u * (unsigned)(t + 1);
            while (*((volatile unsigned*)barp) < tgt) { }
            __threadfence();
        }
        __syncthreads();
    }
}

// ---------------------------------------------------------------------------
// dist = ||h1 - h2||, clip, sigmoid(dist*w + b). Final h lives in g_h buffer 0
// (T=1024 even -> last write went to parity buffer (1024 & 1) = 0).
// ---------------------------------------------------------------------------
__global__ void final_kernel(const float* __restrict__ dw,
                             const float* __restrict__ db,
                             float* __restrict__ out)
{
    int p = blockIdx.x, lane = threadIdx.x;
    const float* h1 = g_h + (size_t)(2 * p) * HID;
    const float* h2 = g_h + (size_t)(2 * p + 1) * HID;
    float s = 0.0f;
    for (int j = lane; j < HID; j += 32) {
        float d = h1[j] - h2[j];
        s += d * d;
    }
    #pragma unroll
    for (int off = 16; off; off >>= 1) s += __shfl_xor_sync(0xffffffffu, s, off);
    if (lane == 0) {
        float dist = sqrtf(s);
        dist = fminf(fmaxf(dist, 1e-7f), 1e7f);
        out[p] = 1.0f / (1.0f + expf(-(dist * dw[0] + db[0])));
    }
}

// ---------------------------------------------------------------------------
extern "C" void kernel_launch(void* const* d_in, const int* in_sizes, int n_in,
                              void* d_out, int out_size)
{
    (void)in_sizes; (void)n_in; (void)out_size;
    const float* x  = (const float*)d_in[0];
    const float* W0 = (const float*)d_in[1];
    const float* U0 = (const float*)d_in[2];
    const float* b0 = (const float*)d_in[3];
    const float* W1 = (const float*)d_in[4];
    const float* U1 = (const float*)d_in[5];
    const float* b1 = (const float*)d_in[6];
    const float* W2 = (const float*)d_in[7];
    const float* U2 = (const float*)d_in[8];
    const float* b2 = (const float*)d_in[9];
    const float* dw = (const float*)d_in[10];
    const float* db = (const float*)d_in[11];
    float* out = (float*)d_out;

    cudaFuncSetAttribute(lstm_layer_kernel,
                         cudaFuncAttributeMaxDynamicSharedMemorySize, 160 * 1024);

    init_kernel<<<8192, 256>>>(x);

    size_t smem128 = (size_t)(48 * 128 + 21536) * sizeof(float);  // 110,720 B
    size_t smem256 = (size_t)(48 * 256 + 21536) * sizeof(float);  // 135,296 B
    lstm_layer_kernel<<<128, 256, smem128>>>(x, 128, W0, U0, b0, 0);
    lstm_layer_kernel<<<128, 256, smem256>>>(x, 256, W1, U1, b1, 1);
    lstm_layer_kernel<<<128, 256, smem256>>>(x, 256, W2, U2, b2, 2);

    final_kernel<<<32, 32>>>(dw, db, out);
}

// round 3
// speedup vs baseline: 1.3482x; 1.3482x over previous
#include <cuda_runtime.h>
#include <cuda_fp16.h>
#include <cstdint>
#include <cstddef>

#define T_SEQ 1024
#define HID   256
#define ROWS  64

// Scratch (sanctioned: __device__ globals)
__device__ float    g_h[2 * ROWS * HID];                       // double-buffered hidden state
__device__ float    g_seqA[(size_t)ROWS * T_SEQ * HID];        // layer0 output (64 MB)
__device__ float    g_seqB[(size_t)ROWS * T_SEQ * HID];        // layer1 output (64 MB)
__device__ float    g_mask[ROWS * T_SEQ];
__device__ unsigned g_bar[12];                                 // [layer][batch-group]

// ---------------------------------------------------------------------------
__global__ void init_kernel(const float* __restrict__ x)
{
    if (blockIdx.x == 0 && threadIdx.x < 12) g_bar[threadIdx.x] = 0u;
    int warp = (int)((blockIdx.x * blockDim.x + threadIdx.x) >> 5);
    int lane = threadIdx.x & 31;
    if (warp < ROWS * T_SEQ) {
        const float4* p = reinterpret_cast<const float4*>(x) + (size_t)warp * 32;
        float4 v = p[lane];
        bool nz = (v.x != 0.0f) || (v.y != 0.0f) || (v.z != 0.0f) || (v.w != 0.0f);
        unsigned bl = __ballot_sync(0xffffffffu, nz);
        if (lane == 0) g_mask[warp] = bl ? 1.0f : 0.0f;
    }
}

// ---------------------------------------------------------------------------
static __device__ __forceinline__ uint32_t smaddr(const void* p)
{
    return (uint32_t)__cvta_generic_to_shared(p);
}

static __device__ __forceinline__ void split2(float a, float b, uint32_t& hi, uint32_t& lo)
{
    __half h0 = __float2half_rn(a), h1 = __float2half_rn(b);
    __half l0 = __float2half_rn(a - __half2float(h0));
    __half l1 = __float2half_rn(b - __half2float(h1));
    __half2 H = __halves2half2(h0, h1), L = __halves2half2(l0, l1);
    hi = *reinterpret_cast<uint32_t*>(&H);
    lo = *reinterpret_cast<uint32_t*>(&L);
}

static __device__ __forceinline__ void ldmx4(uint32_t addr, uint32_t& r0, uint32_t& r1,
                                             uint32_t& r2, uint32_t& r3)
{
    asm volatile("ldmatrix.sync.aligned.m8n8.x4.shared.b16 {%0,%1,%2,%3}, [%4];"
                 : "=r"(r0), "=r"(r1), "=r"(r2), "=r"(r3) : "r"(addr));
}

static __device__ __forceinline__ void mma16816(float* d, uint32_t a0, uint32_t a1,
                                                uint32_t a2, uint32_t a3,
                                                uint32_t b0, uint32_t b1)
{
    asm volatile("mma.sync.aligned.m16n8k16.row.col.f32.f16.f16.f32 "
                 "{%0,%1,%2,%3}, {%4,%5,%6,%7}, {%8,%9}, {%0,%1,%2,%3};"
                 : "+f"(d[0]), "+f"(d[1]), "+f"(d[2]), "+f"(d[3])
                 : "r"(a0), "r"(a1), "r"(a2), "r"(a3), "r"(b0), "r"(b1));
}

static __device__ __forceinline__ float wu_elem(const float* __restrict__ W,
                                                const float* __restrict__ U,
                                                int Kin, int k, int gcol)
{
    return (k < Kin) ? W[(size_t)k * 1024 + gcol] : U[(size_t)(k - Kin) * 1024 + gcol];
}

// ---------------------------------------------------------------------------
// Persistent tensor-core masked-LSTM layer.
// 128 blocks: bg = blockIdx&3 (16 rows), cg = blockIdx>>2 (8 units -> 32 gate cols).
// 8 warps: each computes m16 x n32 with its own K-slice of 16*KSTEPS; weights
// (hi/lo f16 split) live in registers for the whole kernel. A = [x_t ; h] staged
// per step in smem as hi/lo halves; split-precision 3-mma per fragment pair.
// ---------------------------------------------------------------------------
template <int KSTEPS>
__global__ void __launch_bounds__(256, 1)
lstm_tc_kernel(const float* __restrict__ x0,
               const float* __restrict__ W, const float* __restrict__ U,
               const float* __restrict__ bias, int layer)
{
    constexpr int KT  = 128 * KSTEPS;        // total K = Kin + 256
    constexpr int KIN = KT - 256;
    constexpr int LDA = KT + 8;              // halves; +8 => 16B-aligned rows, 4-bank skew

    extern __shared__ unsigned char smraw[];
    __half* Ahi = reinterpret_cast<__half*>(smraw);
    __half* Alo = Ahi + 16 * LDA;
    float*  p_sh = reinterpret_cast<float*>(Alo + 16 * LDA);   // [8][16][36]
    float*  z_sh = p_sh + 8 * 16 * 36;                         // [512]
    float*  b_sh = z_sh + 512;                                 // [32]

    const float* in_seq  = (layer == 0) ? x0 : (layer == 1 ? g_seqA : g_seqB);
    float*       seq_out = (layer == 0) ? g_seqA : (layer == 1 ? g_seqB : nullptr);

    const int tid  = threadIdx.x;
    const int w    = tid >> 5;
    const int lane = tid & 31;
    const int bg   = blockIdx.x & 3;
    const int cg   = blockIdx.x >> 2;
    const int row0 = bg * 16;

    if (tid < 32) b_sh[tid] = bias[((tid >> 3) << 8) + (cg << 3) + (tid & 7)];

    // ---- load weight fragments into registers (hi/lo split), once ----
    const int q  = lane & 3;
    const int nl = lane >> 2;
    uint32_t Bhi[4][KSTEPS][2], Blo[4][KSTEPS][2];
    #pragma unroll
    for (int i = 0; i < 4; i++) {
        int c = i * 8 + nl;
        int gcol = ((c >> 3) << 8) + (cg << 3) + (c & 7);
        #pragma unroll
        for (int s = 0; s < KSTEPS; s++) {
            int kb = w * 16 * KSTEPS + 16 * s + 2 * q;
            split2(wu_elem(W, U, KIN, kb,     gcol),
                   wu_elem(W, U, KIN, kb + 1, gcol), Bhi[i][s][0], Blo[i][s][0]);
            split2(wu_elem(W, U, KIN, kb + 8, gcol),
                   wu_elem(W, U, KIN, kb + 9, gcol), Bhi[i][s][1], Blo[i][s][1]);
        }
    }

    // ldmatrix lane addressing: row = lane&15, k-offset = (lane>>4)*8
    const int lrow = lane & 15;
    const int koff = (lane >> 4) * 8;

    // gate-thread state (tid < 128): (row = tid>>3, unit = tid&7)
    float c_reg = 0.0f, h_reg = 0.0f;

    unsigned* barp = &g_bar[layer * 4 + bg];

    for (int t = 0; t < T_SEQ; t++) {
        // ---- stage A = [x_t ; h(t-1)] as hi/lo halves ----
        {
            constexpr int NX = 16 * (KIN >> 1);
            for (int idx = tid; idx < NX; idx += 256) {
                int r = idx / (KIN >> 1);
                int k = (idx - r * (KIN >> 1)) * 2;
                float2 v = *reinterpret_cast<const float2*>(
                    in_seq + ((size_t)(row0 + r) * T_SEQ + t) * KIN + k);
                uint32_t hi, lo;
                split2(v.x, v.y, hi, lo);
                *reinterpret_cast<uint32_t*>(Ahi + r * LDA + k) = hi;
                *reinterpret_cast<uint32_t*>(Alo + r * LDA + k) = lo;
            }
            if (t == 0) {
                for (int idx = tid; idx < 16 * 128; idx += 256) {
                    int r = idx >> 7, k = (idx & 127) * 2;
                    *reinterpret_cast<uint32_t*>(Ahi + r * LDA + KIN + k) = 0u;
                    *reinterpret_cast<uint32_t*>(Alo + r * LDA + KIN + k) = 0u;
                }
            } else {
                const float* hsrc = g_h + (size_t)(t & 1) * ROWS * HID + row0 * HID;
                for (int idx = tid; idx < 16 * 128; idx += 256) {
                    int r = idx >> 7, k = (idx & 127) * 2;
                    float2 v = *reinterpret_cast<const float2*>(hsrc + r * HID + k);
                    uint32_t hi, lo;
                    split2(v.x, v.y, hi, lo);
                    *reinterpret_cast<uint32_t*>(Ahi + r * LDA + KIN + k) = hi;
                    *reinterpret_cast<uint32_t*>(Alo + r * LDA + KIN + k) = lo;
                }
            }
        }
        __syncthreads();

        // ---- tensor-core GEMM: D[16x32] partial for this warp's K-slice ----
        float D[4][4];
        #pragma unroll
        for (int i = 0; i < 4; i++)
            #pragma unroll
            for (int j = 0; j < 4; j++) D[i][j] = 0.0f;

        #pragma unroll
        for (int s = 0; s < KSTEPS; s++) {
            int k0 = w * 16 * KSTEPS + 16 * s;
            uint32_t ah0, ah1, ah2, ah3, al0, al1, al2, al3;
            ldmx4(smaddr(Ahi + lrow * LDA + k0 + koff), ah0, ah1, ah2, ah3);
            ldmx4(smaddr(Alo + lrow * LDA + k0 + koff), al0, al1, al2, al3);
            #pragma unroll
            for (int i = 0; i < 4; i++) {
                mma16816(D[i], ah0, ah1, ah2, ah3, Bhi[i][s][0], Bhi[i][s][1]);
                mma16816(D[i], al0, al1, al2, al3, Bhi[i][s][0], Bhi[i][s][1]);
                mma16816(D[i], ah0, ah1, ah2, ah3, Blo[i][s][0], Blo[i][s][1]);
            }
        }

        // ---- store warp partials, reduce split-K across 8 warps ----
        #pragma unroll
        for (int i = 0; i < 4; i++) {
            float2 lo2 = make_float2(D[i][0], D[i][1]);
            float2 hi2 = make_float2(D[i][2], D[i][3]);
            *reinterpret_cast<float2*>(&p_sh[((w * 16 + nl) * 36) + i * 8 + 2 * q])     = lo2;
            *reinterpret_cast<float2*>(&p_sh[((w * 16 + nl + 8) * 36) + i * 8 + 2 * q]) = hi2;
        }
        __syncthreads();

        for (int o = tid; o < 512; o += 256) {
            int r = o >> 5, c = o & 31;
            float z = b_sh[c];
            #pragma unroll
            for (int w8 = 0; w8 < 8; w8++) z += p_sh[(w8 * 16 + r) * 36 + c];
            z_sh[o] = z;
        }
        __syncthreads();

        // ---- gates + masked state update (128 threads: 16 rows x 8 units) ----
        if (tid < 128) {
            int blc = tid >> 3, u = tid & 7;
            float zi = z_sh[blc * 32 + u];
            float zf = z_sh[blc * 32 + 8 + u];
            float zg = z_sh[blc * 32 + 16 + u];
            float zo = z_sh[blc * 32 + 24 + u];
            float si = 1.0f / (1.0f + expf(-zi));
            float sf = 1.0f / (1.0f + expf(-zf));
            float so = 1.0f / (1.0f + expf(-zo));
            float cn = sf * c_reg + si * tanhf(zg);
            float hn = so * tanhf(cn);
            float m  = g_mask[(row0 + blc) * T_SEQ + t];
            if (m < 0.5f) { cn = c_reg; hn = h_reg; }     // keras masked carry
            c_reg = cn; h_reg = hn;
            int row = row0 + blc, j = (cg << 3) + u;
            g_h[(size_t)((t + 1) & 1) * ROWS * HID + row * HID + j] = hn;
            if (seq_out) seq_out[((size_t)row * T_SEQ + t) * HID + j] = hn;
        }
        __threadfence();
        __syncthreads();

        // ---- 32-block batch-group barrier ----
        if (tid == 0) {
            atomicAdd(barp, 1u);
            unsigned tgt = 32u * (unsigned)(t + 1);
            while (*((volatile unsigned*)barp) < tgt) { }
            __threadfence();
        }
        __syncthreads();
    }
}

// ---------------------------------------------------------------------------
__global__ void final_kernel(const float* __restrict__ dw,
                             const float* __restrict__ db,
                             float* __restrict__ out)
{
    int p = blockIdx.x, lane = threadIdx.x;
    const float* h1 = g_h + (size_t)(2 * p) * HID;       // parity (1024&1)=0
    const float* h2 = g_h + (size_t)(2 * p + 1) * HID;
    float s = 0.0f;
    for (int j = lane; j < HID; j += 32) {
        float d = h1[j] - h2[j];
        s += d * d;
    }
    #pragma unroll
    for (int off = 16; off; off >>= 1) s += __shfl_xor_sync(0xffffffffu, s, off);
    if (lane == 0) {
        float dist = sqrtf(s);
        dist = fminf(fmaxf(dist, 1e-7f), 1e7f);
        out[p] = 1.0f / (1.0f + expf(-(dist * dw[0] + db[0])));
    }
}

// ---------------------------------------------------------------------------
extern "C" void kernel_launch(void* const* d_in, const int* in_sizes, int n_in,
                              void* d_out, int out_size)
{
    (void)in_sizes; (void)n_in; (void)out_size;
    const float* x  = (const float*)d_in[0];
    const float* W0 = (const float*)d_in[1];
    const float* U0 = (const float*)d_in[2];
    const float* b0 = (const float*)d_in[3];
    const float* W1 = (const float*)d_in[4];
    const float* U1 = (const float*)d_in[5];
    const float* b1 = (const float*)d_in[6];
    const float* W2 = (const float*)d_in[7];
    const float* U2 = (const float*)d_in[8];
    const float* b2 = (const float*)d_in[9];
    const float* dw = (const float*)d_in[10];
    const float* db = (const float*)d_in[11];
    float* out = (float*)d_out;

    // dyn smem: 2*16*LDA halves + (8*16*36 + 512 + 32) floats
    const size_t smem3 = (size_t)64 * (128 * 3 + 8) + (8 * 16 * 36 + 512 + 32) * 4; // 45696
    const size_t smem4 = (size_t)64 * (128 * 4 + 8) + (8 * 16 * 36 + 512 + 32) * 4; // 53888

    cudaFuncSetAttribute(lstm_tc_kernel<3>, cudaFuncAttributeMaxDynamicSharedMemorySize, (int)smem3);
    cudaFuncSetAttribute(lstm_tc_kernel<4>, cudaFuncAttributeMaxDynamicSharedMemorySize, (int)smem4);

    init_kernel<<<8192, 256>>>(x);

    lstm_tc_kernel<3><<<128, 256, smem3>>>(x, W0, U0, b0, 0);
    lstm_tc_kernel<4><<<128, 256, smem4>>>(x, W1, U1, b1, 1);
    lstm_tc_kernel<4><<<128, 256, smem4>>>(x, W2, U2, b2, 2);

    final_kernel<<<32, 32>>>(dw, db, out);
}

// round 4
// speedup vs baseline: 1.7624x; 1.3072x over previous
#include <cuda_runtime.h>
#include <cuda_fp16.h>
#include <cstdint>
#include <cstddef>

#define T_SEQ 1024
#define HID   256
#define ROWS  64

// Scratch (sanctioned: __device__ globals)
__device__ __half   g_h_hi[2 * ROWS * HID];                    // double-buffered hidden (hi)
__device__ __half   g_h_lo[2 * ROWS * HID];                    // double-buffered hidden (lo)
__device__ __half   g_seqA_hi[(size_t)ROWS * T_SEQ * HID];     // layer0 out (32 MB each)
__device__ __half   g_seqA_lo[(size_t)ROWS * T_SEQ * HID];
__device__ __half   g_seqB_hi[(size_t)ROWS * T_SEQ * HID];     // layer1 out
__device__ __half   g_seqB_lo[(size_t)ROWS * T_SEQ * HID];
__device__ float    g_mask[ROWS * T_SEQ];
__device__ unsigned g_bar[12];                                 // [layer][batch-group]

// ---------------------------------------------------------------------------
__global__ void init_kernel(const float* __restrict__ x)
{
    if (blockIdx.x == 0 && threadIdx.x < 12) g_bar[threadIdx.x] = 0u;
    int warp = (int)((blockIdx.x * blockDim.x + threadIdx.x) >> 5);
    int lane = threadIdx.x & 31;
    if (warp < ROWS * T_SEQ) {
        const float4* p = reinterpret_cast<const float4*>(x) + (size_t)warp * 32;
        float4 v = p[lane];
        bool nz = (v.x != 0.0f) || (v.y != 0.0f) || (v.z != 0.0f) || (v.w != 0.0f);
        unsigned bl = __ballot_sync(0xffffffffu, nz);
        if (lane == 0) g_mask[warp] = bl ? 1.0f : 0.0f;
    }
}

// ---------------------------------------------------------------------------
static __device__ __forceinline__ uint32_t smaddr(const void* p)
{
    return (uint32_t)__cvta_generic_to_shared(p);
}

static __device__ __forceinline__ void split2(float a, float b, uint32_t& hi, uint32_t& lo)
{
    __half h0 = __float2half_rn(a), h1 = __float2half_rn(b);
    __half l0 = __float2half_rn(a - __half2float(h0));
    __half l1 = __float2half_rn(b - __half2float(h1));
    __half2 H = __halves2half2(h0, h1), L = __halves2half2(l0, l1);
    hi = *reinterpret_cast<uint32_t*>(&H);
    lo = *reinterpret_cast<uint32_t*>(&L);
}

static __device__ __forceinline__ void ldmx4(uint32_t addr, uint32_t& r0, uint32_t& r1,
                                             uint32_t& r2, uint32_t& r3)
{
    asm volatile("ldmatrix.sync.aligned.m8n8.x4.shared.b16 {%0,%1,%2,%3}, [%4];"
                 : "=r"(r0), "=r"(r1), "=r"(r2), "=r"(r3) : "r"(addr));
}

static __device__ __forceinline__ void mma16816(float* d, uint32_t a0, uint32_t a1,
                                                uint32_t a2, uint32_t a3,
                                                uint32_t b0, uint32_t b1)
{
    asm volatile("mma.sync.aligned.m16n8k16.row.col.f32.f16.f16.f32 "
                 "{%0,%1,%2,%3}, {%4,%5,%6,%7}, {%8,%9}, {%0,%1,%2,%3};"
                 : "+f"(d[0]), "+f"(d[1]), "+f"(d[2]), "+f"(d[3])
                 : "r"(a0), "r"(a1), "r"(a2), "r"(a3), "r"(b0), "r"(b1));
}

static __device__ __forceinline__ float wu_elem(const float* __restrict__ W,
                                                const float* __restrict__ U,
                                                int Kin, int k, int gcol)
{
    return (k < Kin) ? W[(size_t)k * 1024 + gcol] : U[(size_t)(k - Kin) * 1024 + gcol];
}

static __device__ __forceinline__ unsigned ld_acq(const unsigned* p)
{
    unsigned v;
    asm volatile("ld.acquire.gpu.global.u32 %0, [%1];" : "=r"(v) : "l"(p) : "memory");
    return v;
}

static __device__ __forceinline__ void red_rel_add(unsigned* p)
{
    asm volatile("red.release.gpu.global.add.u32 [%0], %1;" :: "l"(p), "r"(1u) : "memory");
}

// ---------------------------------------------------------------------------
// Persistent tensor-core masked-LSTM layer, low-latency L2 rendezvous.
// 128 blocks: bg = blockIdx&3 (16 rows), cg = blockIdx>>2 (8 units -> 32 gate cols).
// 8 warps, split-K: each warp owns an interleaved slice (x-cols + h-cols) so the
// x-part MMA runs BEFORE the h flag-wait. h / inter-layer sequences travel as
// pre-split (hi,lo) f16 pairs through L2 (st.cg / ld.cg, release/acquire flags).
// ---------------------------------------------------------------------------
template <int KSTEPS, bool HALF_IN>
__global__ void __launch_bounds__(256, 1)
lstm_tc_kernel(const float* __restrict__ x0,
               const float* __restrict__ W, const float* __restrict__ U,
               const float* __restrict__ bias, int layer)
{
    constexpr int XSTEPS = KSTEPS - 2;       // 16-wide k-steps in x region per warp
    constexpr int KIN = 128 * XSTEPS;        // 128 (layer0) or 256
    constexpr int KT  = KIN + 256;
    constexpr int LDA = KT + 8;              // halves; rows 16B-aligned, 4-bank skew

    extern __shared__ unsigned char smraw[];
    __half* Ahi = reinterpret_cast<__half*>(smraw);
    __half* Alo = Ahi + 16 * LDA;
    float*  p_sh = reinterpret_cast<float*>(Alo + 16 * LDA);   // [8][16][36]
    float*  z_sh = p_sh + 8 * 16 * 36;                         // [512]
    float*  b_sh = z_sh + 512;                                 // [32]

    const __half* in_hi = (layer == 1) ? g_seqA_hi : g_seqB_hi;
    const __half* in_lo = (layer == 1) ? g_seqA_lo : g_seqB_lo;
    __half* out_hi = (layer == 0) ? g_seqA_hi : (layer == 1 ? g_seqB_hi : nullptr);
    __half* out_lo = (layer == 0) ? g_seqA_lo : (layer == 1 ? g_seqB_lo : nullptr);

    const int tid  = threadIdx.x;
    const int w    = tid >> 5;
    const int lane = tid & 31;
    const int bg   = blockIdx.x & 3;
    const int cg   = blockIdx.x >> 2;
    const int row0 = bg * 16;

    if (tid < 32) b_sh[tid] = bias[((tid >> 3) << 8) + (cg << 3) + (tid & 7)];

    // per-warp K slice base for step s (interleaved: x first, then h)
    auto kbase = [&](int s) -> int {
        return (s < XSTEPS) ? (w * (KIN >> 3) + 16 * s)
                            : (KIN + w * 32 + 16 * (s - XSTEPS));
    };

    // ---- weight fragments into registers (hi/lo split), once ----
    const int q  = lane & 3;
    const int nl = lane >> 2;
    uint32_t Bhi[4][KSTEPS][2], Blo[4][KSTEPS][2];
    #pragma unroll
    for (int i = 0; i < 4; i++) {
        int c = i * 8 + nl;
        int gcol = ((c >> 3) << 8) + (cg << 3) + (c & 7);
        #pragma unroll
        for (int s = 0; s < KSTEPS; s++) {
            int kb = kbase(s) + 2 * q;
            split2(wu_elem(W, U, KIN, kb,     gcol),
                   wu_elem(W, U, KIN, kb + 1, gcol), Bhi[i][s][0], Blo[i][s][0]);
            split2(wu_elem(W, U, KIN, kb + 8, gcol),
                   wu_elem(W, U, KIN, kb + 9, gcol), Bhi[i][s][1], Blo[i][s][1]);
        }
    }

    const int lrow = lane & 15;
    const int koff = (lane >> 4) * 8;

    float c_reg = 0.0f, h_reg = 0.0f;       // gate-thread state (tid<128)
    unsigned* barp = &g_bar[layer * 4 + bg];

    // ---- x staging (step tt) ----
    auto stage_x = [&](int tt) {
        if (HALF_IN) {
            for (int idx = tid; idx < 16 * (KIN / 8); idx += 256) {
                int r = idx / (KIN / 8), kk = idx - r * (KIN / 8);
                size_t base = ((size_t)(row0 + r) * T_SEQ + tt) * (size_t)KIN + kk * 8;
                uint4 vh = *reinterpret_cast<const uint4*>(in_hi + base);
                uint4 vl = *reinterpret_cast<const uint4*>(in_lo + base);
                *reinterpret_cast<uint4*>(Ahi + r * LDA + kk * 8) = vh;
                *reinterpret_cast<uint4*>(Alo + r * LDA + kk * 8) = vl;
            }
        } else {
            for (int idx = tid; idx < 16 * (KIN / 2); idx += 256) {
                int r = idx / (KIN / 2);
                int k = (idx - r * (KIN / 2)) * 2;
                float2 v = *reinterpret_cast<const float2*>(
                    x0 + ((size_t)(row0 + r) * T_SEQ + tt) * KIN + k);
                uint32_t hi, lo;
                split2(v.x, v.y, hi, lo);
                *reinterpret_cast<uint32_t*>(Ahi + r * LDA + k) = hi;
                *reinterpret_cast<uint32_t*>(Alo + r * LDA + k) = lo;
            }
        }
    };

    // ---- pre-loop: zero h staging region, stage x(0) ----
    for (int idx = tid; idx < 16 * 128; idx += 256) {
        int r = idx >> 7, k = (idx & 127) * 2;
        *reinterpret_cast<uint32_t*>(Ahi + r * LDA + KIN + k) = 0u;
        *reinterpret_cast<uint32_t*>(Alo + r * LDA + KIN + k) = 0u;
    }
    stage_x(0);

    for (int t = 0; t < T_SEQ; t++) {
        __syncthreads();                                   // x(t) staged

        // ---- x-part MMAs (independent of flag) ----
        float D[4][4];
        #pragma unroll
        for (int i = 0; i < 4; i++)
            #pragma unroll
            for (int j = 0; j < 4; j++) D[i][j] = 0.0f;

        #pragma unroll
        for (int s = 0; s < XSTEPS; s++) {
            int k0 = kbase(s);
            uint32_t ah0, ah1, ah2, ah3, al0, al1, al2, al3;
            ldmx4(smaddr(Ahi + lrow * LDA + k0 + koff), ah0, ah1, ah2, ah3);
            ldmx4(smaddr(Alo + lrow * LDA + k0 + koff), al0, al1, al2, al3);
            #pragma unroll
            for (int i = 0; i < 4; i++) {
                mma16816(D[i], ah0, ah1, ah2, ah3, Bhi[i][s][0], Bhi[i][s][1]);
                mma16816(D[i], al0, al1, al2, al3, Bhi[i][s][0], Bhi[i][s][1]);
                mma16816(D[i], ah0, ah1, ah2, ah3, Blo[i][s][0], Blo[i][s][1]);
            }
        }

        // ---- wait for h(t-1) publication (acquire) ----
        if (t > 0 && tid == 0) {
            unsigned tgt = 32u * (unsigned)t;
            while (ld_acq(barp) < tgt) { }
        }
        __syncthreads();

        // ---- stage h(t-1) from L2 (pre-split halves) ----
        if (t > 0) {
            const __half* hh = g_h_hi + ((size_t)((t & 1) * ROWS) + row0) * HID;
            const __half* hl = g_h_lo + ((size_t)((t & 1) * ROWS) + row0) * HID;
            for (int idx = tid; idx < 16 * 32; idx += 256) {
                int r = idx >> 5, kk = idx & 31;
                uint4 vh = __ldcg(reinterpret_cast<const uint4*>(hh + r * HID) + kk);
                uint4 vl = __ldcg(reinterpret_cast<const uint4*>(hl + r * HID) + kk);
                *reinterpret_cast<uint4*>(Ahi + r * LDA + KIN + kk * 8) = vh;
                *reinterpret_cast<uint4*>(Alo + r * LDA + KIN + kk * 8) = vl;
            }
        }
        __syncthreads();

        // ---- h-part MMAs ----
        #pragma unroll
        for (int s = XSTEPS; s < KSTEPS; s++) {
            int k0 = kbase(s);
            uint32_t ah0, ah1, ah2, ah3, al0, al1, al2, al3;
            ldmx4(smaddr(Ahi + lrow * LDA + k0 + koff), ah0, ah1, ah2, ah3);
            ldmx4(smaddr(Alo + lrow * LDA + k0 + koff), al0, al1, al2, al3);
            #pragma unroll
            for (int i = 0; i < 4; i++) {
                mma16816(D[i], ah0, ah1, ah2, ah3, Bhi[i][s][0], Bhi[i][s][1]);
                mma16816(D[i], al0, al1, al2, al3, Bhi[i][s][0], Bhi[i][s][1]);
                mma16816(D[i], ah0, ah1, ah2, ah3, Blo[i][s][0], Blo[i][s][1]);
            }
        }

        // ---- warp partials + split-K reduce ----
        #pragma unroll
        for (int i = 0; i < 4; i++) {
            *reinterpret_cast<float2*>(&p_sh[((w * 16 + nl) * 36) + i * 8 + 2 * q]) =
                make_float2(D[i][0], D[i][1]);
            *reinterpret_cast<float2*>(&p_sh[((w * 16 + nl + 8) * 36) + i * 8 + 2 * q]) =
                make_float2(D[i][2], D[i][3]);
        }
        __syncthreads();

        for (int o = tid; o < 512; o += 256) {
            int r = o >> 5, c = o & 31;
            float z = b_sh[c];
            #pragma unroll
            for (int w8 = 0; w8 < 8; w8++) z += p_sh[(w8 * 16 + r) * 36 + c];
            z_sh[o] = z;
        }
        __syncthreads();

        // ---- gates + masked state update + publish (st.cg, pre-split halves) ----
        if (tid < 128) {
            int blc = tid >> 3, u = tid & 7;
            float zi = z_sh[blc * 32 + u];
            float zf = z_sh[blc * 32 + 8 + u];
            float zg = z_sh[blc * 32 + 16 + u];
            float zo = z_sh[blc * 32 + 24 + u];
            float si = 1.0f / (1.0f + expf(-zi));
            float sf = 1.0f / (1.0f + expf(-zf));
            float so = 1.0f / (1.0f + expf(-zo));
            float cn = sf * c_reg + si * tanhf(zg);
            float hn = so * tanhf(cn);
            float m  = g_mask[(row0 + blc) * T_SEQ + t];
            if (m < 0.5f) { cn = c_reg; hn = h_reg; }       // keras masked carry
            c_reg = cn; h_reg = hn;

            __half hh = __float2half_rn(hn);
            __half hl = __float2half_rn(hn - __half2float(hh));
            int row = row0 + blc, j = (cg << 3) + u;
            size_t hidx = ((size_t)(((t + 1) & 1) * ROWS) + row) * HID + j;
            __stcg(reinterpret_cast<short*>(g_h_hi) + hidx, __half_as_short(hh));
            __stcg(reinterpret_cast<short*>(g_h_lo) + hidx, __half_as_short(hl));
            if (out_hi) {
                size_t sidx = ((size_t)row * T_SEQ + t) * HID + j;
                __stcg(reinterpret_cast<short*>(out_hi) + sidx, __half_as_short(hh));
                __stcg(reinterpret_cast<short*>(out_lo) + sidx, __half_as_short(hl));
            }
        }
        __syncthreads();                                    // all publishes issued

        if (tid == 0) red_rel_add(barp);                    // release: h(t) visible

        if (t + 1 < T_SEQ) stage_x(t + 1);                  // prefetch next x
    }
}

// ---------------------------------------------------------------------------
__global__ void final_kernel(const float* __restrict__ dw,
                             const float* __restrict__ db,
                             float* __restrict__ out)
{
    int p = blockIdx.x, lane = threadIdx.x;
    // last publish at t=1023 -> parity (1024&1)=0 buffer
    const __half* h1h = g_h_hi + (size_t)(2 * p) * HID;
    const __half* h1l = g_h_lo + (size_t)(2 * p) * HID;
    const __half* h2h = g_h_hi + (size_t)(2 * p + 1) * HID;
    const __half* h2l = g_h_lo + (size_t)(2 * p + 1) * HID;
    float s = 0.0f;
    for (int j = lane; j < HID; j += 32) {
        float a = __half2float(h1h[j]) + __half2float(h1l[j]);
        float b = __half2float(h2h[j]) + __half2float(h2l[j]);
        float d = a - b;
        s += d * d;
    }
    #pragma unroll
    for (int off = 16; off; off >>= 1) s += __shfl_xor_sync(0xffffffffu, s, off);
    if (lane == 0) {
        float dist = sqrtf(s);
        dist = fminf(fmaxf(dist, 1e-7f), 1e7f);
        out[p] = 1.0f / (1.0f + expf(-(dist * dw[0] + db[0])));
    }
}

// ---------------------------------------------------------------------------
extern "C" void kernel_launch(void* const* d_in, const int* in_sizes, int n_in,
                              void* d_out, int out_size)
{
    (void)in_sizes; (void)n_in; (void)out_size;
    const float* x  = (const float*)d_in[0];
    const float* W0 = (const float*)d_in[1];
    const float* U0 = (const float*)d_in[2];
    const float* b0 = (const float*)d_in[3];
    const float* W1 = (const float*)d_in[4];
    const float* U1 = (const float*)d_in[5];
    const float* b1 = (const float*)d_in[6];
    const float* W2 = (const float*)d_in[7];
    const float* U2 = (const float*)d_in[8];
    const float* b2 = (const float*)d_in[9];
    const float* dw = (const float*)d_in[10];
    const float* db = (const float*)d_in[11];
    float* out = (float*)d_out;

    const size_t smem3 = (size_t)64 * (128 * 3 + 8) + (8 * 16 * 36 + 512 + 32) * 4; // 45696
    const size_t smem4 = (size_t)64 * (128 * 4 + 8) + (8 * 16 * 36 + 512 + 32) * 4; // 53888

    cudaFuncSetAttribute(lstm_tc_kernel<3, false>,
                         cudaFuncAttributeMaxDynamicSharedMemorySize, (int)smem3);
    cudaFuncSetAttribute(lstm_tc_kernel<4, true>,
                         cudaFuncAttributeMaxDynamicSharedMemorySize, (int)smem4);

    init_kernel<<<8192, 256>>>(x);

    lstm_tc_kernel<3, false><<<128, 256, smem3>>>(x, W0, U0, b0, 0);
    lstm_tc_kernel<4, true ><<<128, 256, smem4>>>(x, W1, U1, b1, 1);
    lstm_tc_kernel<4, true ><<<128, 256, smem4>>>(x, W2, U2, b2, 2);

    final_kernel<<<32, 32>>>(dw, db, out);
}